// round 5
// baseline (speedup 1.0000x reference)
#include <cuda_runtime.h>
#include <cuda_bf16.h>

// Shapes (fixed by setup_inputs): B=4, H=12, N=4096, D=64, E=32
#define BB   4
#define HH   12
#define NN   4096
#define DD   64
#define EE   32
#define TWOE 64
#define TILE 128   // tokens per block == threads per block

// Output layout (concatenated flattened tuple, fp32):
#define SZ_HDE  (24576ll)                          // 12*64*32
#define OFF_ES  (12582912ll)
#define OFF_RS  (18874368ll)
#define OFF_WE0 (25165824ll)
#define OFF_WR0 (25190400ll)
#define OFF_Q   (25214976ll)
#define OFF_K   (37797888ll)
#define OFF_LAM (50380800ll)

typedef unsigned long long u64;

__device__ __forceinline__ u64 pack2(float lo, float hi) {
    u64 r;
    asm("mov.b64 %0, {%1, %2};" : "=l"(r) : "f"(lo), "f"(hi));
    return r;
}
__device__ __forceinline__ void unpack2(u64 v, float& lo, float& hi) {
    asm("mov.b64 {%0, %1}, %2;" : "=f"(lo), "=f"(hi) : "l"(v));
}
// Packed dual-fp32 FMA (sm_100+): d.lo = a.lo*b.lo + c.lo ; d.hi = a.hi*b.hi + c.hi
__device__ __forceinline__ u64 fma2(u64 a, u64 b, u64 c) {
    u64 d;
    asm("fma.rn.f32x2 %0, %1, %2, %3;" : "=l"(d) : "l"(a), "l"(b), "l"(c));
    return d;
}

__global__ __launch_bounds__(TILE) void pca_fused_kernel(
    const float* __restrict__ Q, const float* __restrict__ K,
    const float* __restrict__ we, const float* __restrict__ wr,
    const float* __restrict__ mask, const float* __restrict__ W,
    const float* __restrict__ bias, float* __restrict__ out)
{
    const int tileIdx = blockIdx.x;   // 0..31
    const int h       = blockIdx.y;   // 0..11
    const int b       = blockIdx.z;   // 0..3
    const int tid     = threadIdx.x;  // 0..127

    __shared__ __align__(16) float s_we[DD * EE];   // we[0][h][d][e]
    __shared__ __align__(16) float s_wr[DD * EE];   // wr[0][h][d][e]
    __shared__ __align__(16) float s_Wt[TWOE * DD]; // Wt[j][d] = W[d][j]
    __shared__ __align__(16) float s_b[DD];

    // ---- stage weights into smem ----
    {
        const float* we_h = we + (long long)h * DD * EE;
        const float* wr_h = wr + (long long)h * DD * EE;
        #pragma unroll
        for (int i = tid; i < DD * EE; i += TILE) {
            s_we[i] = we_h[i];
            s_wr[i] = wr_h[i];
        }
        #pragma unroll
        for (int i = tid; i < TWOE * DD; i += TILE) {
            int j = i >> 6;        // column of W (0..63)
            int d = i & 63;        // row of W    (0..63)
            s_Wt[i] = W[d * TWOE + j];
        }
        if (tid < DD) s_b[tid] = bias[tid];
    }
    __syncthreads();

    const int n = tileIdx * TILE + tid;
    const long long bh     = (long long)(b * HH + h);
    const long long rowOff = (bh * NN + n) * DD;
    const long long erow   = (bh * NN + n) * EE;

    float* out_attn = out;
    float* out_es   = out + OFF_ES;
    float* out_rs   = out + OFF_RS;
    float* out_q    = out + OFF_Q;
    float* out_k    = out + OFF_K;

    const u64* s_we2 = (const u64*)s_we;   // [d][16] packed pairs along e
    const u64* s_wr2 = (const u64*)s_wr;
    const u64* s_Wt2 = (const u64*)s_Wt;   // [j][32] packed pairs along d
    const u64* s_b2  = (const u64*)s_b;

    u64 e2[EE / 2];   // escore packed pairs
    u64 r2[EE / 2];   // rscore packed pairs

    // ================= Q phase: normalize -> queries out, escore =================
    {
        float q[DD];
        const float4* src = (const float4*)(Q + rowOff);
        #pragma unroll
        for (int i = 0; i < DD / 4; ++i) {
            float4 v = src[i];
            q[4*i] = v.x; q[4*i+1] = v.y; q[4*i+2] = v.z; q[4*i+3] = v.w;
        }
        float ss = 0.f;
        #pragma unroll
        for (int i = 0; i < DD; ++i) ss = fmaf(q[i], q[i], ss);
        float inv = rsqrtf(fmaxf(ss, 1e-24f));   // ss = ||x||^2; matches max(||x||,1e-12)
        #pragma unroll
        for (int i = 0; i < DD; ++i) q[i] *= inv;

        float4* dq = (float4*)(out_q + rowOff);
        #pragma unroll
        for (int i = 0; i < DD / 4; ++i)
            dq[i] = make_float4(q[4*i], q[4*i+1], q[4*i+2], q[4*i+3]);

        #pragma unroll
        for (int j = 0; j < EE / 2; ++j) e2[j] = 0ull;
        #pragma unroll 4
        for (int d = 0; d < DD; ++d) {
            u64 qd2 = pack2(q[d], q[d]);
            const u64* row = s_we2 + d * (EE / 2);
            #pragma unroll
            for (int j = 0; j < EE / 2; ++j)
                e2[j] = fma2(qd2, row[j], e2[j]);
        }
        float4* de = (float4*)(out_es + erow);
        #pragma unroll
        for (int i = 0; i < EE / 4; ++i) {
            float a0, a1, a2, a3;
            unpack2(e2[2*i],   a0, a1);
            unpack2(e2[2*i+1], a2, a3);
            de[i] = make_float4(a0, a1, a2, a3);
        }
    }

    // ================= K phase: normalize -> keys out, rscore =================
    {
        float k[DD];
        const float4* src = (const float4*)(K + rowOff);
        #pragma unroll
        for (int i = 0; i < DD / 4; ++i) {
            float4 v = src[i];
            k[4*i] = v.x; k[4*i+1] = v.y; k[4*i+2] = v.z; k[4*i+3] = v.w;
        }
        float ss = 0.f;
        #pragma unroll
        for (int i = 0; i < DD; ++i) ss = fmaf(k[i], k[i], ss);
        float inv = rsqrtf(fmaxf(ss, 1e-24f));
        #pragma unroll
        for (int i = 0; i < DD; ++i) k[i] *= inv;

        float4* dk = (float4*)(out_k + rowOff);
        #pragma unroll
        for (int i = 0; i < DD / 4; ++i)
            dk[i] = make_float4(k[4*i], k[4*i+1], k[4*i+2], k[4*i+3]);

        #pragma unroll
        for (int j = 0; j < EE / 2; ++j) r2[j] = 0ull;
        #pragma unroll 4
        for (int d = 0; d < DD; ++d) {
            u64 kd2 = pack2(k[d], k[d]);
            const u64* row = s_wr2 + d * (EE / 2);
            #pragma unroll
            for (int j = 0; j < EE / 2; ++j)
                r2[j] = fma2(kd2, row[j], r2[j]);
        }
        float4* dr = (float4*)(out_rs + erow);
        #pragma unroll
        for (int i = 0; i < EE / 4; ++i) {
            float a0, a1, a2, a3;
            unpack2(r2[2*i],   a0, a1);
            unpack2(r2[2*i+1], a2, a3);
            dr[i] = make_float4(a0, a1, a2, a3);
        }
    }

    // ================= attn phase: (score @ W^T + b) * mask =================
    // Two 32-wide halves of D to bound register pressure; packed pairs along d.
    {
        const float m = mask[(long long)b * NN + n];
        float4* da = (float4*)(out_attn + rowOff);

        #pragma unroll
        for (int half = 0; half < 2; ++half) {
            const int p0 = half * 16;   // pair offset within a Wt row (32 pairs/row)
            u64 acc[16];
            #pragma unroll
            for (int j = 0; j < 16; ++j) acc[j] = s_b2[p0 + j];

            #pragma unroll 2
            for (int e = 0; e < EE; ++e) {
                float slo, shi;
                unpack2(e2[e >> 1], slo, shi);
                float s = (e & 1) ? shi : slo;
                u64 s2 = pack2(s, s);
                const u64* row = s_Wt2 + e * (DD / 2) + p0;
                #pragma unroll
                for (int j = 0; j < 16; ++j)
                    acc[j] = fma2(s2, row[j], acc[j]);
            }
            #pragma unroll 2
            for (int e = 0; e < EE; ++e) {
                float slo, shi;
                unpack2(r2[e >> 1], slo, shi);
                float s = (e & 1) ? shi : slo;
                u64 s2 = pack2(s, s);
                const u64* row = s_Wt2 + (EE + e) * (DD / 2) + p0;
                #pragma unroll
                for (int j = 0; j < 16; ++j)
                    acc[j] = fma2(s2, row[j], acc[j]);
            }

            #pragma unroll
            for (int i = 0; i < 8; ++i) {
                float a0, a1, a2, a3;
                unpack2(acc[2*i],   a0, a1);
                unpack2(acc[2*i+1], a2, a3);
                da[half * 8 + i] = make_float4(a0 * m, a1 * m, a2 * m, a3 * m);
            }
        }
    }
}

extern "C" void kernel_launch(void* const* d_in, const int* in_sizes, int n_in,
                              void* d_out, int out_size) {
    const float* Q    = (const float*)d_in[0];
    const float* K    = (const float*)d_in[1];
    const float* we   = (const float*)d_in[2];
    const float* wr   = (const float*)d_in[3];
    const float* mask = (const float*)d_in[4];
    const float* W    = (const float*)d_in[5];
    const float* bias = (const float*)d_in[6];
    const float* Lam  = (const float*)d_in[7];
    float* out = (float*)d_out;

    dim3 grid(NN / TILE, HH, BB);   // 32 x 12 x 4
    pca_fused_kernel<<<grid, TILE>>>(Q, K, we, wr, mask, W, bias, out);

    // Pass-through outputs: we[0], wr[0], Lambda (device-to-device, capturable)
    cudaMemcpyAsync(out + OFF_WE0, we,  SZ_HDE * sizeof(float), cudaMemcpyDeviceToDevice);
    cudaMemcpyAsync(out + OFF_WR0, wr,  SZ_HDE * sizeof(float), cudaMemcpyDeviceToDevice);
    cudaMemcpyAsync(out + OFF_LAM, Lam, 384 * sizeof(float),    cudaMemcpyDeviceToDevice);
}

// round 12
// speedup vs baseline: 1.2132x; 1.2132x over previous
#include <cuda_runtime.h>
#include <cuda_bf16.h>

// Shapes (fixed by setup_inputs): B=4, H=12, N=4096, D=64, E=32
#define BB   4
#define HH   12
#define NN   4096
#define DD   64
#define EE   32
#define TWOE 64
#define TILE 128   // tokens per block == threads per block

// Output layout (concatenated flattened tuple, fp32):
#define SZ_HDE  (24576ll)                          // 12*64*32
#define OFF_ES  (12582912ll)
#define OFF_RS  (18874368ll)
#define OFF_WE0 (25165824ll)
#define OFF_WR0 (25190400ll)
#define OFF_Q   (25214976ll)
#define OFF_K   (37797888ll)
#define OFF_LAM (50380800ll)

// Dynamic smem layout (float offsets)
#define SM_WE    0        // we[h]  : 64*32 = 2048 floats
#define SM_WR    2048     // wr[h]  : 2048 floats
#define SM_WT    4096     // W^T    : 64*64 = 4096 floats
#define SM_B     8192     // bias   : 64 floats
#define SM_STAGE 8256     // staging: 128 rows * 16 float4 = 8192 floats (32 KB)
#define SMEM_BYTES ((SM_STAGE + 8192) * 4)   // 65792 B

typedef unsigned long long u64;

__device__ __forceinline__ u64 pack2(float lo, float hi) {
    u64 r;
    asm("mov.b64 %0, {%1, %2};" : "=l"(r) : "f"(lo), "f"(hi));
    return r;
}
__device__ __forceinline__ void unpack2(u64 v, float& lo, float& hi) {
    asm("mov.b64 {%0, %1}, %2;" : "=f"(lo), "=f"(hi) : "l"(v));
}
// Packed dual-fp32 FMA (sm_100+): exact IEEE fp32 on both lanes.
__device__ __forceinline__ u64 fma2(u64 a, u64 b, u64 c) {
    u64 d;
    asm("fma.rn.f32x2 %0, %1, %2, %3;" : "=l"(d) : "l"(a), "l"(b), "l"(c));
    return d;
}

// XOR swizzle: 16-chunk rows (64-float rows) and 8-chunk rows (32-float rows).
// Conflict-free for both row-private access (fixed c, lanes = consecutive r)
// and coalesced access (fixed r per 8-lane phase, consecutive c).
__device__ __forceinline__ int sw16(int r, int c) { return (r << 4) | ((c ^ r) & 15); }
__device__ __forceinline__ int sw8 (int r, int c) { return (r << 3) | ((c ^ r) & 7); }

__global__ __launch_bounds__(TILE) void pca_fused_kernel(
    const float* __restrict__ Q, const float* __restrict__ K,
    const float* __restrict__ we, const float* __restrict__ wr,
    const float* __restrict__ mask, const float* __restrict__ W,
    const float* __restrict__ bias, float* __restrict__ out)
{
    extern __shared__ float sm[];
    float* s_we = sm + SM_WE;
    float* s_wr = sm + SM_WR;
    float* s_Wt = sm + SM_WT;
    float* s_b  = sm + SM_B;
    float4* stg = (float4*)(sm + SM_STAGE);   // 128 x 16 float4

    const int tileIdx = blockIdx.x;   // 0..31
    const int h       = blockIdx.y;   // 0..11
    const int b       = blockIdx.z;   // 0..3
    const int tid     = threadIdx.x;  // 0..127

    const int base = tileIdx * TILE;
    const long long bh      = (long long)(b * HH + h);
    const long long tileOff = (bh * NN + base) * DD;   // tile start in [B,H,N,D]
    const long long eOff    = (bh * NN + base) * EE;   // tile start in [B,H,N,E]

    // ---- stage weights into smem + Q tile copy-in (coalesced) ----
    {
        const float* we_h = we + (long long)h * DD * EE;
        const float* wr_h = wr + (long long)h * DD * EE;
        #pragma unroll
        for (int i = tid; i < DD * EE; i += TILE) {
            s_we[i] = we_h[i];
            s_wr[i] = wr_h[i];
        }
        #pragma unroll
        for (int i = tid; i < TWOE * DD; i += TILE) {
            int j = i >> 6;        // column of W (0..63)
            int d = i & 63;        // row of W    (0..63)
            s_Wt[i] = W[d * TWOE + j];
        }
        if (tid < DD) s_b[tid] = bias[tid];

        const float4* gq = (const float4*)(Q + tileOff);
        #pragma unroll
        for (int it = 0; it < 16; ++it) {
            int j = tid + it * TILE;               // 2048 chunks
            stg[sw16(j >> 4, j & 15)] = gq[j];
        }
    }
    __syncthreads();

    float* out_attn = out;
    float* out_es   = out + OFF_ES;
    float* out_rs   = out + OFF_RS;
    float* out_q    = out + OFF_Q;
    float* out_k    = out + OFF_K;

    float esc[EE];   // escore scalars (kept for attn phase)
    float rsc[EE];   // rscore scalars

    // ================= Q phase =================
    {
        float q[DD];
        #pragma unroll
        for (int c = 0; c < 16; ++c) {           // row-private swizzled LDS.128
            float4 v = stg[sw16(tid, c)];
            q[4*c] = v.x; q[4*c+1] = v.y; q[4*c+2] = v.z; q[4*c+3] = v.w;
        }
        float ss = 0.f;
        #pragma unroll
        for (int i = 0; i < DD; ++i) ss = fmaf(q[i], q[i], ss);
        float inv = rsqrtf(fmaxf(ss, 1e-24f));   // ss = ||x||^2; matches max(||x||,1e-12)
        #pragma unroll
        for (int i = 0; i < DD; ++i) q[i] *= inv;

        // escore: q . we[:,e]
        u64 e2[EE / 2];
        #pragma unroll
        for (int j = 0; j < EE / 2; ++j) e2[j] = 0ull;
        #pragma unroll 8
        for (int d = 0; d < DD; ++d) {
            u64 qd2 = pack2(q[d], q[d]);
            const ulonglong2* row = (const ulonglong2*)(s_we + d * EE);  // 8 x LDS.128
            #pragma unroll
            for (int j = 0; j < 8; ++j) {
                ulonglong2 w = row[j];
                e2[2*j]   = fma2(qd2, w.x, e2[2*j]);
                e2[2*j+1] = fma2(qd2, w.y, e2[2*j+1]);
            }
        }
        #pragma unroll
        for (int i = 0; i < EE / 2; ++i) unpack2(e2[i], esc[2*i], esc[2*i+1]);

        // write normalized q back to OWN row (row-private: no sync needed)
        #pragma unroll
        for (int c = 0; c < 16; ++c)
            stg[sw16(tid, c)] = make_float4(q[4*c], q[4*c+1], q[4*c+2], q[4*c+3]);
    }
    __syncthreads();
    {   // q copy-out (coalesced)
        float4* gqo = (float4*)(out_q + tileOff);
        #pragma unroll
        for (int it = 0; it < 16; ++it) {
            int j = tid + it * TILE;
            gqo[j] = stg[sw16(j >> 4, j & 15)];
        }
    }
    __syncthreads();

    // ================= K phase =================
    {   // K copy-in (coalesced)
        const float4* gk = (const float4*)(K + tileOff);
        #pragma unroll
        for (int it = 0; it < 16; ++it) {
            int j = tid + it * TILE;
            stg[sw16(j >> 4, j & 15)] = gk[j];
        }
    }
    __syncthreads();
    {
        float k[DD];
        #pragma unroll
        for (int c = 0; c < 16; ++c) {
            float4 v = stg[sw16(tid, c)];
            k[4*c] = v.x; k[4*c+1] = v.y; k[4*c+2] = v.z; k[4*c+3] = v.w;
        }
        float ss = 0.f;
        #pragma unroll
        for (int i = 0; i < DD; ++i) ss = fmaf(k[i], k[i], ss);
        float inv = rsqrtf(fmaxf(ss, 1e-24f));
        #pragma unroll
        for (int i = 0; i < DD; ++i) k[i] *= inv;

        u64 r2[EE / 2];
        #pragma unroll
        for (int j = 0; j < EE / 2; ++j) r2[j] = 0ull;
        #pragma unroll 8
        for (int d = 0; d < DD; ++d) {
            u64 kd2 = pack2(k[d], k[d]);
            const ulonglong2* row = (const ulonglong2*)(s_wr + d * EE);
            #pragma unroll
            for (int j = 0; j < 8; ++j) {
                ulonglong2 w = row[j];
                r2[2*j]   = fma2(kd2, w.x, r2[2*j]);
                r2[2*j+1] = fma2(kd2, w.y, r2[2*j+1]);
            }
        }
        #pragma unroll
        for (int i = 0; i < EE / 2; ++i) unpack2(r2[i], rsc[2*i], rsc[2*i+1]);

        #pragma unroll
        for (int c = 0; c < 16; ++c)
            stg[sw16(tid, c)] = make_float4(k[4*c], k[4*c+1], k[4*c+2], k[4*c+3]);
    }
    __syncthreads();
    {   // k copy-out
        float4* gko = (float4*)(out_k + tileOff);
        #pragma unroll
        for (int it = 0; it < 16; ++it) {
            int j = tid + it * TILE;
            gko[j] = stg[sw16(j >> 4, j & 15)];
        }
    }
    __syncthreads();

    // ================= attn phase: (score @ W^T + b) * mask =================
    {
        const float m = mask[(long long)b * NN + base + tid];   // coalesced
        const ulonglong2* b2 = (const ulonglong2*)s_b;

        #pragma unroll
        for (int half = 0; half < 2; ++half) {
            u64 acc[16];
            #pragma unroll
            for (int j = 0; j < 8; ++j) {
                ulonglong2 bb = b2[half * 8 + j];
                acc[2*j]   = bb.x;
                acc[2*j+1] = bb.y;
            }
            #pragma unroll 4
            for (int e = 0; e < EE; ++e) {
                u64 s2 = pack2(esc[e], esc[e]);
                const ulonglong2* row = (const ulonglong2*)(s_Wt + e * DD) + half * 8;
                #pragma unroll
                for (int j = 0; j < 8; ++j) {
                    ulonglong2 w = row[j];
                    acc[2*j]   = fma2(s2, w.x, acc[2*j]);
                    acc[2*j+1] = fma2(s2, w.y, acc[2*j+1]);
                }
            }
            #pragma unroll 4
            for (int e = 0; e < EE; ++e) {
                u64 s2 = pack2(rsc[e], rsc[e]);
                const ulonglong2* row = (const ulonglong2*)(s_Wt + (EE + e) * DD) + half * 8;
                #pragma unroll
                for (int j = 0; j < 8; ++j) {
                    ulonglong2 w = row[j];
                    acc[2*j]   = fma2(s2, w.x, acc[2*j]);
                    acc[2*j+1] = fma2(s2, w.y, acc[2*j+1]);
                }
            }
            // stage masked result into OWN row
            #pragma unroll
            for (int j = 0; j < 8; ++j) {
                float a0, a1, a2, a3;
                unpack2(acc[2*j],   a0, a1);
                unpack2(acc[2*j+1], a2, a3);
                stg[sw16(tid, half * 8 + j)] = make_float4(a0*m, a1*m, a2*m, a3*m);
            }
        }
    }
    __syncthreads();
    {   // attn copy-out
        float4* gao = (float4*)(out_attn + tileOff);
        #pragma unroll
        for (int it = 0; it < 16; ++it) {
            int j = tid + it * TILE;
            gao[j] = stg[sw16(j >> 4, j & 15)];
        }
    }
    __syncthreads();

    // ================= es / rs copy-out (8-chunk rows, both in one buffer) =================
    {
        float4* stgE = stg;          // es: rows 0..127 -> 1024 chunks (16 KB)
        float4* stgR = stg + 1024;   // rs: next 16 KB
        #pragma unroll
        for (int c = 0; c < 8; ++c)
            stgE[sw8(tid, c)] = make_float4(esc[4*c], esc[4*c+1], esc[4*c+2], esc[4*c+3]);
        #pragma unroll
        for (int c = 0; c < 8; ++c)
            stgR[sw8(tid, c)] = make_float4(rsc[4*c], rsc[4*c+1], rsc[4*c+2], rsc[4*c+3]);
        __syncthreads();
        float4* ges = (float4*)(out_es + eOff);
        float4* grs = (float4*)(out_rs + eOff);
        #pragma unroll
        for (int it = 0; it < 8; ++it) {
            int j = tid + it * TILE;              // 1024 chunks each
            ges[j] = stgE[sw8(j >> 3, j & 7)];
            grs[j] = stgR[sw8(j >> 3, j & 7)];
        }
    }
}

extern "C" void kernel_launch(void* const* d_in, const int* in_sizes, int n_in,
                              void* d_out, int out_size) {
    const float* Q    = (const float*)d_in[0];
    const float* K    = (const float*)d_in[1];
    const float* we   = (const float*)d_in[2];
    const float* wr   = (const float*)d_in[3];
    const float* mask = (const float*)d_in[4];
    const float* W    = (const float*)d_in[5];
    const float* bias = (const float*)d_in[6];
    const float* Lam  = (const float*)d_in[7];
    float* out = (float*)d_out;

    cudaFuncSetAttribute(pca_fused_kernel,
                         cudaFuncAttributeMaxDynamicSharedMemorySize, SMEM_BYTES);

    dim3 grid(NN / TILE, HH, BB);   // 32 x 12 x 4
    pca_fused_kernel<<<grid, TILE, SMEM_BYTES>>>(Q, K, we, wr, mask, W, bias, out);

    // Pass-through outputs: we[0], wr[0], Lambda (device-to-device, capturable)
    cudaMemcpyAsync(out + OFF_WE0, we,  SZ_HDE * sizeof(float), cudaMemcpyDeviceToDevice);
    cudaMemcpyAsync(out + OFF_WR0, wr,  SZ_HDE * sizeof(float), cudaMemcpyDeviceToDevice);
    cudaMemcpyAsync(out + OFF_LAM, Lam, 384 * sizeof(float),    cudaMemcpyDeviceToDevice);
}